// round 17
// baseline (speedup 1.0000x reference)
#include <cuda_runtime.h>
#include <cstdint>
#include <math.h>

#define EMBED   2048
#define NEXP    64
#define TOPK    8
#define BM      128
#define BK      32
#define NCHUNK  (EMBED / BK)      // 64
#define ABYTES  16384             // A: 128 tokens x 128B
#define STAGE_B 24576             // A 16KB + B 8KB
#define NSTAGE  4
#define SMEM_BYTES (NSTAGE * STAGE_B)   // 98304

typedef unsigned long long ull;

__device__ __forceinline__ uint32_t smem_u32(const void* p) {
    uint32_t a;
    asm("{ .reg .u64 t; cvta.to.shared.u64 t, %1; cvt.u32.u64 %0, t; }" : "=r"(a) : "l"(p));
    return a;
}
// packed dual-fp32 FMA (Blackwell f32x2 pipe, full fp32 per lane)
__device__ __forceinline__ void fma2(ull& c, ull a, ull b) {
    asm("fma.rn.f32x2 %0, %1, %2, %0;" : "+l"(c) : "l"(a), "l"(b));
}
__device__ __forceinline__ void cpa8(uint32_t dst, const void* src) {
    asm volatile("cp.async.ca.shared.global [%0], [%1], 8;" :: "r"(dst), "l"(src));
}
__device__ __forceinline__ float accf(ull v) {   // lo + hi halves
    return __uint_as_float((uint32_t)v) + __uint_as_float((uint32_t)(v >> 32));
}

__global__ __launch_bounds__(256, 2)
void router_f32x2(const float* __restrict__ X,
                  const float* __restrict__ W,
                  const float* __restrict__ bias,
                  float* __restrict__ out,
                  int M, int write_idx)
{
    extern __shared__ float sm[];          // 96 KB: 4 stages; reused for scores
    const uint32_t smb = smem_u32(sm);
    const int tid  = threadIdx.x;
    const int m0   = blockIdx.x * BM;
    const int lane = tid & 31;
    const int tg   = tid >> 5;             // warp: tokens tg*16 .. +15
    const int th   = lane >> 4;            // token half: 8 tokens
    const int eh   = lane & 15;            // expert quad: 4*eh .. 4*eh+3
    const int rotk = tg * 2 + th;          // A rotation key == (token >> 3)

    // ---- producer addressing ----
    // A: token t row = 128B of 8 16B-units; unit i (kpairs 2i,2i+1) stored at
    //    t*128 + ((i + (t>>3))&7)*16  (rotation de-conflicts th=0/1 dual-address loads)
    // B: kpair p row = 512B; ull of expert e at position pos(u=e>>1) = (u>>1)+(u&1)*16:
    //    even units at positions 0-15, odd at 16-31 -> consumer reads are base+imm,
    //    8 distinct bank-quads per phase (fixes R15's even-quad conflict).
    const int t0 = tid >> 4;               // 0..15
    const int pq = tid & 15;               // k-pair
    const float* xp = X + (size_t)(m0 + t0) * EMBED + pq * 2;
    const float* wp = W + (size_t)t0 * EMBED + pq * 2;
    uint32_t adst[8];
    #pragma unroll
    for (int j = 0; j < 8; j++) {          // token t0+16j
        const int t = t0 + 16 * j;
        adst[j] = (uint32_t)(t * 128 + (((pq >> 1) + (t >> 3)) & 7) * 16 + (pq & 1) * 8);
    }
    // B: expert e = t0 + 16j; pos = (e>>2) + ((e>>1)&1)*16; j-step: +(16>>2)*16B = +64B
    const uint32_t bdst0 = (uint32_t)(ABYTES + pq * 512
                         + ((t0 >> 2) + ((t0 >> 1) & 1) * 16) * 16 + (t0 & 1) * 8);

    auto issue = [&](int c) {
        const int k0 = c * BK;
        const uint32_t sb = smb + (uint32_t)(c & 3) * STAGE_B;
        #pragma unroll
        for (int j = 0; j < 8; j++)        // A: tokens t0 + 16j
            cpa8(sb + adst[j], xp + (size_t)j * 16 * EMBED + k0);
        #pragma unroll
        for (int j = 0; j < 4; j++)        // B: experts t0 + 16j (+64B per step)
            cpa8(sb + bdst0 + j * 64u, wp + (size_t)j * 16 * EMBED + k0);
    };

    ull acc[8][4];                         // [token][expert] = (even-k, odd-k) sums
    #pragma unroll
    for (int i = 0; i < 8; i++)
        #pragma unroll
        for (int j = 0; j < 4; j++) acc[i][j] = 0ull;

    issue(0); asm volatile("cp.async.commit_group;");
    issue(1); asm volatile("cp.async.commit_group;");
    issue(2); asm volatile("cp.async.commit_group;");

    for (int c = 0; c < NCHUNK; c++) {
        if (c > 0 && c + 2 < NCHUNK) {     // stage (c+2)&3 free since chunk c-2 (prev barrier)
            issue(c + 2);
            asm volatile("cp.async.commit_group;");
        }
        if (c + 2 < NCHUNK)      asm volatile("cp.async.wait_group 2;");
        else if (c + 1 < NCHUNK) asm volatile("cp.async.wait_group 1;");
        else                     asm volatile("cp.async.wait_group 0;");
        __syncthreads();                   // stage c visible to all warps

        const char* Ab = (const char*)sm + (c & 3) * STAGE_B + tg * 2048 + th * 1024;
        const char* Bb = (const char*)sm + (c & 3) * STAGE_B + ABYTES + eh * 16;
        #pragma unroll
        for (int pp = 0; pp < 8; pp++) {   // 2 kpairs (p0, p1) per step
            const int p0 = 2 * pp, p1 = 2 * pp + 1;
            // B: 4 LDS.128, base+immediate, conflict-free (quads 0..7 per phase)
            const ulonglong2 b0a = *(const ulonglong2*)(Bb + p0 * 512);        // exp 4eh..4eh+1, p0
            const ulonglong2 b0b = *(const ulonglong2*)(Bb + p0 * 512 + 256);  // exp 4eh+2..3,  p0
            const ulonglong2 b1a = *(const ulonglong2*)(Bb + p1 * 512);        // exp 4eh..4eh+1, p1
            const ulonglong2 b1b = *(const ulonglong2*)(Bb + p1 * 512 + 256);  // exp 4eh+2..3,  p1
            const int ro = ((pp + rotk) & 7) * 16;     // A unit rotation
            #pragma unroll
            for (int tt = 0; tt < 8; tt++) {
                // A: 1 LDS.128, 2 addresses (th=0/1) in different bank quads -> 1 wf
                const ulonglong2 au = *(const ulonglong2*)(Ab + tt * 128 + ro);
                fma2(acc[tt][0], au.x, b0a.x);   // exp 4eh,   kpair p0
                fma2(acc[tt][1], au.x, b0a.y);   // exp 4eh+1, kpair p0
                fma2(acc[tt][2], au.x, b0b.x);   // exp 4eh+2, kpair p0
                fma2(acc[tt][3], au.x, b0b.y);   // exp 4eh+3, kpair p0
                fma2(acc[tt][0], au.y, b1a.x);   // exp 4eh,   kpair p1
                fma2(acc[tt][1], au.y, b1a.y);
                fma2(acc[tt][2], au.y, b1b.x);
                fma2(acc[tt][3], au.y, b1b.y);
            }
        }
    }
    __syncthreads();                       // all warps done with final stage

    // ---------- stage scores (row stride 68; writes land outside live stage data) ----------
    #pragma unroll
    for (int tt = 0; tt < 8; tt++) {
        float4 v;
        v.x = accf(acc[tt][0]); v.y = accf(acc[tt][1]);
        v.z = accf(acc[tt][2]); v.w = accf(acc[tt][3]);
        *(float4*)(sm + (tg * 16 + th * 8 + tt) * 68 + eh * 4) = v;
    }
    if (tid < NEXP) sm[8704 + tid] = bias[tid];
    __syncthreads();

    // ---------- per-token top-8 + masked softmax (verified R1/R8-R16) ----------
    if (tid < BM) {
        const int r = tid;
        float sc[64];
        #pragma unroll
        for (int jj = 0; jj < 16; jj++) {
            float4 v  = *(const float4*)(sm + r * 68 + jj * 4);
            float4 bv = *(const float4*)(sm + 8704 + jj * 4);
            sc[jj * 4 + 0] = v.x + bv.x;
            sc[jj * 4 + 1] = v.y + bv.y;
            sc[jj * 4 + 2] = v.z + bv.z;
            sc[jj * 4 + 3] = v.w + bv.w;
        }

        float vals[TOPK];
        int   idxs[TOPK];
        #pragma unroll
        for (int i = 0; i < TOPK; i++) { vals[i] = -INFINITY; idxs[i] = 0; }
        #pragma unroll
        for (int j = 0; j < NEXP; j++) {
            float s = sc[j];
            if (s > vals[TOPK - 1]) {            // strict > : ties keep lower index
                vals[TOPK - 1] = s; idxs[TOPK - 1] = j;
                #pragma unroll
                for (int q = TOPK - 1; q > 0; q--) {
                    if (vals[q] > vals[q - 1]) {
                        float tv = vals[q]; vals[q] = vals[q - 1]; vals[q - 1] = tv;
                        int   ti = idxs[q]; idxs[q] = idxs[q - 1]; idxs[q - 1] = ti;
                    }
                }
            }
        }

        const float mx   = fmaxf(vals[0], 0.f);
        const float base = expf(-mx);
        float den = (float)(NEXP - TOPK) * base;
        float ev[TOPK];
        #pragma unroll
        for (int i = 0; i < TOPK; i++) { ev[i] = expf(vals[i] - mx); den += ev[i]; }
        const float inv = 1.f / den;
        const float bz  = base * inv;

        const int token = m0 + r;
        float* orow = out + (size_t)token * NEXP;
        #pragma unroll
        for (int j = 0; j < NEXP; j += 4) {
            float4 v; v.x = bz; v.y = bz; v.z = bz; v.w = bz;
            *(float4*)(orow + j) = v;
        }
        #pragma unroll
        for (int i = 0; i < TOPK; i++)
            orow[idxs[i]] = ev[i] * inv;

        if (write_idx) {
            float* oi = out + (size_t)M * NEXP + (size_t)token * TOPK;
            #pragma unroll
            for (int i = 0; i < TOPK; i++) oi[i] = (float)idxs[i];
        }
    }
}

extern "C" void kernel_launch(void* const* d_in, const int* in_sizes, int n_in,
                              void* d_out, int out_size) {
    const float* X = (const float*)d_in[0];
    const float* W = (const float*)d_in[1];
    const float* b = (const float*)d_in[2];
    int M = in_sizes[0] / EMBED;                        // 32768 tokens
    int write_idx = (out_size >= M * (NEXP + TOPK)) ? 1 : 0;

    cudaFuncSetAttribute(router_f32x2, cudaFuncAttributeMaxDynamicSharedMemorySize, SMEM_BYTES);
    router_f32x2<<<M / BM, 256, SMEM_BYTES>>>(X, W, b, (float*)d_out, M, write_idx);
}